// round 4
// baseline (speedup 1.0000x reference)
#include <cuda_runtime.h>
#include <math.h>

// YOLO loss: preds/targets [N,7,7,30] fp32 -> scalar fp32.
// Streaming HBM-bound reduction. Two kernels: main (per-block partials) + reduce.

constexpr int D   = 30;    // floats per cell
constexpr int BLK = 128;   // threads per block == cells per block
constexpr float LAMBDA_NOOBJ = 0.5f;
constexpr float EPS_IOU      = 1e-10f;

constexpr int MAX_BLOCKS = 16384;
__device__ float g_part[MAX_BLOCKS];

__global__ void __launch_bounds__(BLK)
yolo_main_kernel(const float* __restrict__ preds,
                 const float* __restrict__ targets,
                 int n_cells)
{
    // Contiguous staging (same layout as global) -> STS.128 stores.
    __shared__ float sp[BLK * D];
    __shared__ float st[BLK * D];
    __shared__ float warp_sums[BLK / 32];

    const int tid   = threadIdx.x;
    const int cell0 = blockIdx.x * BLK;

    float loss = 0.0f;   // accumulates class loss during load + per-cell terms later

    // ---- Stage 1: coalesced global -> smem (identity layout), fused class loss ----
    if (cell0 + BLK <= n_cells) {
        const float4* p4 = reinterpret_cast<const float4*>(preds   + (size_t)cell0 * D);
        const float4* t4 = reinterpret_cast<const float4*>(targets + (size_t)cell0 * D);
        float4* sp4 = reinterpret_cast<float4*>(sp);
        float4* st4 = reinterpret_cast<float4*>(st);
        constexpr int NV = BLK * D / 4;          // 960 float4 per array
        #pragma unroll
        for (int it = 0; it < (NV + BLK - 1) / BLK; ++it) {
            int i = tid + it * BLK;
            if (i < NV) {
                float4 vp = p4[i];
                float4 vt = t4[i];
                sp4[i] = vp;
                st4[i] = vt;
                // fused class loss: channel j = (4i+k) mod 30, class iff j >= 10
                int f = i * 4;
                int c = f / D;
                int j = f - c * D;               // even, 0..28
                float d;
                d = vp.x - vt.x; if (j     >= 10) loss += d * d;
                d = vp.y - vt.y; if (j + 1 >= 10) loss += d * d;   // j+1 <= 29, no wrap
                int j2 = (j + 2 >= D) ? j + 2 - D : j + 2;
                int j3 = (j + 3 >= D) ? j + 3 - D : j + 3;
                d = vp.z - vt.z; if (j2    >= 10) loss += d * d;
                d = vp.w - vt.w; if (j3    >= 10) loss += d * d;
            }
        }
    } else {
        // Tail block: guarded scalar path (same fused class loss).
        int lim = (n_cells - cell0) * D;
        for (int f = tid; f < BLK * D; f += BLK) {
            int c = f / D;
            int j = f - c * D;
            float vp = 0.f, vt = 0.f;
            if (f < lim) {
                vp = preds  [(size_t)cell0 * D + f];
                vt = targets[(size_t)cell0 * D + f];
            }
            sp[f] = vp;
            st[f] = vt;
            if (j >= 10) { float d = vp - vt; loss += d * d; }
        }
    }
    __syncthreads();

    // ---- Stage 2: per-cell box/conf terms (one thread per cell) ----
    if (cell0 + tid < n_cells) {
        const float* p = sp + tid * D;
        const float* t = st + tid * D;

        // IoU for the 2 paired boxes
        float iou[2];
        #pragma unroll
        for (int b = 0; b < 2; ++b) {
            float px = p[5*b + 0], py = p[5*b + 1], pw = p[5*b + 2], ph = p[5*b + 3];
            float tx = t[5*b + 0], ty = t[5*b + 1], tw = t[5*b + 2], th = t[5*b + 3];
            float iw = fminf(px + 0.5f*pw, tx + 0.5f*tw) - fmaxf(px - 0.5f*pw, tx - 0.5f*tw);
            float ih = fminf(py + 0.5f*ph, ty + 0.5f*th) - fmaxf(py - 0.5f*ph, ty - 0.5f*th);
            iw = fmaxf(0.0f, iw);
            ih = fmaxf(0.0f, ih);
            float inter = iw * ih;
            float uni   = pw * ph + tw * th - inter;
            iou[b] = inter / (uni + EPS_IOU);
        }

        // argmax over 2 boxes (first max on ties -> strict >)
        int sel = (iou[1] > iou[0]) ? 1 : 0;

        // coord loss, masked by has_obj = targets[...,4] > 0
        bool has_obj = (t[4] > 0.0f);
        float dx = p[5*sel + 0] - t[5*sel + 0];
        float dy = p[5*sel + 1] - t[5*sel + 1];
        if (has_obj) loss += dx*dx + dy*dy;

        // target-class argmax (first max on ties), pcgt = p at that index
        float best = t[10];
        int   gt   = 10;
        #pragma unroll
        for (int c = 1; c < 20; ++c) {
            float tc = t[10 + c];
            if (tc > best) { best = tc; gt = 10 + c; }
        }
        float pcgt = p[gt];

        // confidence loss: w * (iou*pcgt - iou)^2 = w * iou^2 * (pcgt-1)^2
        float g = pcgt - 1.0f;
        #pragma unroll
        for (int b = 0; b < 2; ++b) {
            float w    = (b == sel) ? 1.0f : LAMBDA_NOOBJ;
            float diff = iou[b] * g;
            loss += w * diff * diff;
        }
    }

    // ---- Stage 3: block reduction -> per-block partial (no atomics, no zeroing) ----
    #pragma unroll
    for (int off = 16; off > 0; off >>= 1)
        loss += __shfl_xor_sync(0xFFFFFFFFu, loss, off);
    if ((tid & 31) == 0) warp_sums[tid >> 5] = loss;
    __syncthreads();
    if (tid == 0) {
        float s = 0.0f;
        #pragma unroll
        for (int w = 0; w < BLK / 32; ++w) s += warp_sums[w];
        g_part[blockIdx.x] = s;
    }
}

__global__ void __launch_bounds__(1024)
yolo_reduce_kernel(float* __restrict__ out, int nblocks, int N)
{
    __shared__ double ws[32];
    int tid = threadIdx.x;

    double s = 0.0;
    for (int i = tid; i < nblocks; i += 1024)
        s += (double)g_part[i];

    #pragma unroll
    for (int off = 16; off > 0; off >>= 1)
        s += __shfl_xor_sync(0xFFFFFFFFu, s, off);
    if ((tid & 31) == 0) ws[tid >> 5] = s;
    __syncthreads();
    if (tid == 0) {
        double tot = 0.0;
        #pragma unroll
        for (int w = 0; w < 32; ++w) tot += ws[w];
        out[0] = (float)(tot / (double)N);
    }
}

extern "C" void kernel_launch(void* const* d_in, const int* in_sizes, int n_in,
                              void* d_out, int out_size)
{
    const float* preds   = (const float*)d_in[0];
    const float* targets = (const float*)d_in[1];
    float* out = (float*)d_out;

    int total   = in_sizes[0];          // N*7*7*30
    int n_cells = total / D;            // N*49
    int N       = total / (7 * 7 * D);  // batch

    int grid = (n_cells + BLK - 1) / BLK;
    if (grid > MAX_BLOCKS) grid = MAX_BLOCKS;   // safety; not hit for this shape

    yolo_main_kernel<<<grid, BLK>>>(preds, targets, n_cells);
    yolo_reduce_kernel<<<1, 1024>>>(out, grid, N);
}